// round 2
// baseline (speedup 1.0000x reference)
#include <cuda_runtime.h>
#include <math.h>

// Problem constants
#define T_STEPS 300
#define BATCH   64
#define NH      512
#define D_IN    10
#define D_OUT   2
#define ALPHA_F 0.2f

#define OUTS_SZ (T_STEPS*BATCH*D_OUT)
#define RSZ     (T_STEPS*BATCH*NH)
#define BN      (BATCH*NH)

// Persistent device scratch (allowed: __device__ globals, no allocation)
__device__ float g_X[3][BATCH][NH];        // hidden pre-activations: [m1, pmd, s1]
__device__ float g_Wm1pmd_c[NH*NH];        // W_m1_pmd + W_out @ W_fb  (feedback folded)
__device__ float g_bias_pmd[NH];           // b_m1_pmd+b_s1_pmd+b_fb + b_out@W_fb (t>=2)
__device__ float g_bias_pmd_t1[NH];        // b_m1_pmd+b_s1_pmd+b_fb             (t==1)

// ---------------------------------------------------------------------------
// Prep: fold feedback into m1->pmd weight, fold biases, zero state and t=0
// output slices. Runs once per launch (graph-captured), makes every replay
// deterministic.
// ---------------------------------------------------------------------------
__global__ void prep_kernel(const float* __restrict__ W_m1_pmd,
                            const float* __restrict__ W_out,   // [NH][2]
                            const float* __restrict__ W_fb,    // [2][NH]
                            const float* __restrict__ b_m1_pmd,
                            const float* __restrict__ b_s1_pmd,
                            const float* __restrict__ b_fb,
                            const float* __restrict__ b_out,
                            float* __restrict__ d_out)
{
    int idx = blockIdx.x*blockDim.x + threadIdx.x;
    int nth = gridDim.x*blockDim.x;

    for (int i = idx; i < NH*NH; i += nth) {
        int k = i >> 9;
        int j = i & (NH-1);
        g_Wm1pmd_c[i] = W_m1_pmd[i]
                      + W_out[k*2+0]*W_fb[j]
                      + W_out[k*2+1]*W_fb[NH+j];
    }
    for (int j = idx; j < NH; j += nth) {
        float base = b_m1_pmd[j] + b_s1_pmd[j] + b_fb[j];
        g_bias_pmd_t1[j] = base;
        g_bias_pmd[j]    = base + b_out[0]*W_fb[j] + b_out[1]*W_fb[NH+j];
    }
    float* Xf = &g_X[0][0][0];
    for (int i = idx; i < 3*BN; i += nth) Xf[i] = 0.0f;

    float* r0_m1  = d_out + OUTS_SZ;
    float* r0_pmd = r0_m1 + RSZ;
    float* r0_s1  = r0_pmd + RSZ;
    for (int i = idx; i < BN; i += nth) {
        r0_m1[i]  = 0.0f;
        r0_pmd[i] = 0.0f;
        r0_s1[i]  = 0.0f;
    }
}

// ---------------------------------------------------------------------------
// One RNN timestep. Grid = 192 blocks:
//   blocks [0,64)   : pmd region (3 source matmuls)  -- heaviest, launched first
//   blocks [64,128) : m1 region  (2 source matmuls)
//   blocks [128,192): s1 region  (1 source matmul + DIN=10 input term)
// Block = 256 threads = 2 K-halves x 128; each thread accumulates a 2x2 tile
// (rows 2bb,2bb+1 ; cols j0,j0+1) -> inner loop is 2 LDS.64 + 4 FFMA per k.
// A tiles stored k-major with stride 66 (float2-aligned, conflict-free reads).
// Double-buffered LDG->STS prefetch hides L2 latency under tile compute.
// ---------------------------------------------------------------------------
__global__ void __launch_bounds__(256) step_kernel(
    int t,
    const float* __restrict__ W_rec_m1,
    const float* __restrict__ W_pmd_m1,
    const float* __restrict__ b_pmd_m1,
    const float* __restrict__ W_rec_pmd,
    const float* __restrict__ W_s1_pmd,
    const float* __restrict__ W_rec_s1,
    const float* __restrict__ W_in_s1,
    const float* __restrict__ b_in_s1,
    const float* __restrict__ stim,
    float* __restrict__ d_out)
{
    __shared__ float As [2][2][32][66];   // [kh][buf][kk][b] k-major, pad 66
    __shared__ float Wsm[2][2][32][8];    // [kh][buf][kk][j]
    __shared__ float stim_s[BATCH*D_IN];  // current stimulus (s1 blocks)
    __shared__ float red[128][4];         // K-half reduction

    float* r_m1  = d_out + OUTS_SZ;
    float* r_pmd = r_m1 + RSZ;
    float* r_s1  = r_pmd + RSZ;
    const float* rp_m1  = r_m1  + (size_t)(t-1)*BN;
    const float* rp_pmd = r_pmd + (size_t)(t-1)*BN;
    const float* rp_s1  = r_s1  + (size_t)(t-1)*BN;

    const int bid = blockIdx.x;
    const int tid = threadIdx.x;
    const int kh  = tid >> 7;      // K-half: k in [kh*256, kh*256+256)
    const int u   = tid & 127;

    const float* Asrc[3];
    const float* Wsrc[3];
    int nsrc, reg, jbase;
    const float* bias;
    float* rout;

    if (bid < 64) {                         // pmd
        reg = 1; nsrc = 3; jbase = bid*8;
        Asrc[0]=rp_pmd; Wsrc[0]=W_rec_pmd;
        Asrc[1]=rp_m1;  Wsrc[1]=g_Wm1pmd_c;   // feedback folded in
        Asrc[2]=rp_s1;  Wsrc[2]=W_s1_pmd;
        bias = (t==1) ? g_bias_pmd_t1 : g_bias_pmd;
        rout = r_pmd + (size_t)t*BN;
    } else if (bid < 128) {                 // m1
        reg = 0; nsrc = 2; jbase = (bid-64)*8;
        Asrc[0]=rp_m1;  Wsrc[0]=W_rec_m1;
        Asrc[1]=rp_pmd; Wsrc[1]=W_pmd_m1;
        Asrc[2]=rp_m1;  Wsrc[2]=W_rec_m1;    // unused
        bias = b_pmd_m1;
        rout = r_m1 + (size_t)t*BN;
    } else {                                // s1
        reg = 2; nsrc = 1; jbase = (bid-128)*8;
        Asrc[0]=rp_s1; Wsrc[0]=W_rec_s1;
        Asrc[1]=rp_s1; Wsrc[1]=W_rec_s1;     // unused
        Asrc[2]=rp_s1; Wsrc[2]=W_rec_s1;     // unused
        bias = b_in_s1;
        rout = r_s1 + (size_t)t*BN;
    }

    // Load-thread mapping
    const int lane8 = u & 7;       // float4 lane within a row (8 x 4 = 32 k)
    const int arow  = u >> 3;      // 0..15 -> row = p*16 + arow
    const int wkk   = u >> 2;      // 0..31
    const int wj    = (u & 3)*2;

    // Compute-thread mapping (2x2 tile)
    const int bb = u >> 2;         // rows 2bb, 2bb+1
    const int jj = u & 3;          // cols jbase+2jj, +1

    float4 a_stage[4];
    float2 w_stage;

    const int nt = nsrc*8;         // 8 k-tiles of 32 per source per half

    auto load_tile = [&](int ti) {
        int s  = ti >> 3;
        int k0 = kh*256 + (ti & 7)*32;
        const float* A = Asrc[s];
        #pragma unroll
        for (int p = 0; p < 4; p++) {
            int b = p*16 + arow;
            a_stage[p] = *reinterpret_cast<const float4*>(&A[b*NH + k0 + lane8*4]);
        }
        w_stage = *reinterpret_cast<const float2*>(&Wsrc[s][(k0 + wkk)*NH + jbase + wj]);
    };
    auto store_tile = [&](int buf) {
        #pragma unroll
        for (int p = 0; p < 4; p++) {
            int b = p*16 + arow;
            As[kh][buf][lane8*4+0][b] = a_stage[p].x;
            As[kh][buf][lane8*4+1][b] = a_stage[p].y;
            As[kh][buf][lane8*4+2][b] = a_stage[p].z;
            As[kh][buf][lane8*4+3][b] = a_stage[p].w;
        }
        *reinterpret_cast<float2*>(&Wsm[kh][buf][wkk][wj]) = w_stage;
    };

    float acc00=0.f, acc01=0.f, acc10=0.f, acc11=0.f;

    // Prologue
    load_tile(0);
    store_tile(0);
    if (reg == 2) {
        for (int i = tid; i < BATCH*D_IN; i += 256)
            stim_s[i] = stim[t*BATCH*D_IN + i];
    }
    __syncthreads();

    for (int ti = 0; ti < nt; ti++) {
        int buf = ti & 1;
        if (ti + 1 < nt) load_tile(ti + 1);       // prefetch next (LDG in flight)
        #pragma unroll
        for (int kk = 0; kk < 32; kk++) {
            float2 a = *reinterpret_cast<const float2*>(&As [kh][buf][kk][2*bb]);
            float2 w = *reinterpret_cast<const float2*>(&Wsm[kh][buf][kk][2*jj]);
            acc00 = fmaf(a.x, w.x, acc00);
            acc01 = fmaf(a.x, w.y, acc01);
            acc10 = fmaf(a.y, w.x, acc10);
            acc11 = fmaf(a.y, w.y, acc11);
        }
        if (ti + 1 < nt) store_tile(buf ^ 1);     // fill other buffer
        __syncthreads();
    }

    // Reduce the two K-halves
    if (kh == 1) {
        red[u][0]=acc00; red[u][1]=acc01; red[u][2]=acc10; red[u][3]=acc11;
    }
    __syncthreads();
    if (kh == 0) {
        acc00 += red[u][0]; acc01 += red[u][1];
        acc10 += red[u][2]; acc11 += red[u][3];

        const int r0 = 2*bb, r1 = 2*bb + 1;
        const int j0 = jbase + 2*jj, j1 = j0 + 1;

        float b0 = bias[j0], b1 = bias[j1];
        float t00 = acc00 + b0, t01 = acc01 + b1;
        float t10 = acc10 + b0, t11 = acc11 + b1;

        if (reg == 2) {   // s1 input term, K = 10
            #pragma unroll
            for (int k = 0; k < D_IN; k++) {
                float w0 = W_in_s1[k*NH + j0];
                float w1 = W_in_s1[k*NH + j1];
                float s0 = stim_s[r0*D_IN + k];
                float s1v = stim_s[r1*D_IN + k];
                t00 = fmaf(s0,  w0, t00);
                t01 = fmaf(s0,  w1, t01);
                t10 = fmaf(s1v, w0, t10);
                t11 = fmaf(s1v, w1, t11);
            }
        }

        float x00 = g_X[reg][r0][j0], x01 = g_X[reg][r0][j1];
        float x10 = g_X[reg][r1][j0], x11 = g_X[reg][r1][j1];
        x00 = (1.0f-ALPHA_F)*x00 + ALPHA_F*t00;
        x01 = (1.0f-ALPHA_F)*x01 + ALPHA_F*t01;
        x10 = (1.0f-ALPHA_F)*x10 + ALPHA_F*t10;
        x11 = (1.0f-ALPHA_F)*x11 + ALPHA_F*t11;
        g_X[reg][r0][j0] = x00;  g_X[reg][r0][j1] = x01;
        g_X[reg][r1][j0] = x10;  g_X[reg][r1][j1] = x11;

        rout[r0*NH + j0] = tanhf(x00);
        rout[r0*NH + j1] = tanhf(x01);
        rout[r1*NH + j0] = tanhf(x10);
        rout[r1*NH + j1] = tanhf(x11);
    }
}

// ---------------------------------------------------------------------------
// Readout over all timesteps: outs[t] = r_m1[t] @ W_out + b_out (t>=1), 0 at t=0.
// One block per t, 128 threads = 64 batch x 2 outputs.
// ---------------------------------------------------------------------------
__global__ void finale_kernel(const float* __restrict__ W_out,
                              const float* __restrict__ b_out,
                              float* __restrict__ d_out)
{
    const int t = blockIdx.x;
    const int u = threadIdx.x;       // 0..127
    const int b = u >> 1, d = u & 1;

    if (t == 0) { d_out[u] = 0.0f; return; }   // out0 = zeros exactly

    const float* rm = d_out + OUTS_SZ + (size_t)t*BN + b*NH;
    float a0=0.f, a1=0.f, a2=0.f, a3=0.f;
    for (int k = 0; k < NH; k += 4) {
        float4 r4 = *reinterpret_cast<const float4*>(&rm[k]);
        a0 = fmaf(r4.x, W_out[(k+0)*2 + d], a0);
        a1 = fmaf(r4.y, W_out[(k+1)*2 + d], a1);
        a2 = fmaf(r4.z, W_out[(k+2)*2 + d], a2);
        a3 = fmaf(r4.w, W_out[(k+3)*2 + d], a3);
    }
    d_out[t*BATCH*D_OUT + b*D_OUT + d] = b_out[d] + (a0 + a1) + (a2 + a3);
}

// ---------------------------------------------------------------------------
// Launch: prep -> 299 step kernels -> readout. All graph-capturable, no
// allocation, no sync, deterministic.
// ---------------------------------------------------------------------------
extern "C" void kernel_launch(void* const* d_in, const int* in_sizes, int n_in,
                              void* d_out, int out_size)
{
    const float* stim      = (const float*)d_in[0];
    const float* W_rec_m1  = (const float*)d_in[1];
    const float* W_rec_pmd = (const float*)d_in[2];
    const float* W_rec_s1  = (const float*)d_in[3];
    const float* W_pmd_m1  = (const float*)d_in[4];
    const float* b_pmd_m1  = (const float*)d_in[5];
    const float* W_m1_pmd  = (const float*)d_in[6];
    const float* b_m1_pmd  = (const float*)d_in[7];
    const float* W_s1_pmd  = (const float*)d_in[8];
    const float* b_s1_pmd  = (const float*)d_in[9];
    const float* W_in_s1   = (const float*)d_in[10];
    const float* b_in_s1   = (const float*)d_in[11];
    const float* W_out_m1  = (const float*)d_in[12];
    const float* b_out_m1  = (const float*)d_in[13];
    const float* W_fb_pmd  = (const float*)d_in[14];
    const float* b_fb_pmd  = (const float*)d_in[15];
    float* out = (float*)d_out;

    prep_kernel<<<256, 256>>>(W_m1_pmd, W_out_m1, W_fb_pmd,
                              b_m1_pmd, b_s1_pmd, b_fb_pmd, b_out_m1, out);

    for (int t = 1; t < T_STEPS; t++) {
        step_kernel<<<192, 256>>>(t,
            W_rec_m1, W_pmd_m1, b_pmd_m1,
            W_rec_pmd, W_s1_pmd,
            W_rec_s1, W_in_s1, b_in_s1,
            stim, out);
    }

    finale_kernel<<<T_STEPS, 128>>>(W_out_m1, b_out_m1, out);
}

// round 3
// speedup vs baseline: 1.4582x; 1.4582x over previous
#include <cuda_runtime.h>
#include <math.h>

// Problem constants
#define T_STEPS 300
#define BATCH   64
#define NH      512
#define D_IN    10
#define D_OUT   2

#define OUTS_SZ (T_STEPS*BATCH*D_OUT)
#define RSZ     (T_STEPS*BATCH*NH)
#define BN      (BATCH*NH)

typedef unsigned long long u64;

// Persistent device scratch (no allocation — __device__ globals)
__device__ float g_X[3][BATCH][NH];          // hidden pre-activations [m1,pmd,s1]
__device__ float g_rA[2][3][NH][BATCH];      // rates, k-major, double-buffered by t parity
__device__ float g_Wm1pmd_c[NH*NH];          // W_m1_pmd + W_out @ W_fb (feedback folded)
__device__ float g_bias_pmd[NH];             // pmd bias for t>=2 (incl b_out@W_fb)
__device__ float g_bias_pmd_t1[NH];          // pmd bias for t==1 (out_prev = 0)

// ---- f32x2 packed math (sm_103a) -----------------------------------------
__device__ __forceinline__ u64 pk2(float x, float y) {
    u64 r; asm("mov.b64 %0,{%1,%2};" : "=l"(r) : "f"(x), "f"(y)); return r;
}
__device__ __forceinline__ float2 upk2(u64 v) {
    float2 r; asm("mov.b64 {%0,%1},%2;" : "=f"(r.x), "=f"(r.y) : "l"(v)); return r;
}
__device__ __forceinline__ void fma2(u64 &d, u64 a, u64 b) {
    asm("fma.rn.f32x2 %0,%1,%2,%0;" : "+l"(d) : "l"(a), "l"(b));
}
__device__ __forceinline__ u64 add2(u64 a, u64 b) {
    u64 d; asm("add.rn.f32x2 %0,%1,%2;" : "=l"(d) : "l"(a), "l"(b)); return d;
}

// ---------------------------------------------------------------------------
// Prep: fold feedback into m1->pmd weight, fold biases, zero state, zero
// k-major rate buffer (parity 0 = r[0] = 0), zero t=0 rate slices in d_out.
// ---------------------------------------------------------------------------
__global__ void prep_kernel(const float* __restrict__ W_m1_pmd,
                            const float* __restrict__ W_out,   // [NH][2]
                            const float* __restrict__ W_fb,    // [2][NH]
                            const float* __restrict__ b_m1_pmd,
                            const float* __restrict__ b_s1_pmd,
                            const float* __restrict__ b_fb,
                            const float* __restrict__ b_out,
                            float* __restrict__ d_out)
{
    int idx = blockIdx.x*blockDim.x + threadIdx.x;
    int nth = gridDim.x*blockDim.x;

    for (int i = idx; i < NH*NH; i += nth) {
        int k = i >> 9;
        int j = i & (NH-1);
        g_Wm1pmd_c[i] = W_m1_pmd[i]
                      + W_out[k*2+0]*W_fb[j]
                      + W_out[k*2+1]*W_fb[NH+j];
    }
    for (int j = idx; j < NH; j += nth) {
        float base = b_m1_pmd[j] + b_s1_pmd[j] + b_fb[j];
        g_bias_pmd_t1[j] = base;
        g_bias_pmd[j]    = base + b_out[0]*W_fb[j] + b_out[1]*W_fb[NH+j];
    }
    float* Xf = &g_X[0][0][0];
    for (int i = idx; i < 3*BN; i += nth) Xf[i] = 0.0f;

    float* rA0 = &g_rA[0][0][0][0];
    for (int i = idx; i < 3*NH*BATCH; i += nth) rA0[i] = 0.0f;

    float* r0_m1  = d_out + OUTS_SZ;
    float* r0_pmd = r0_m1 + RSZ;
    float* r0_s1  = r0_pmd + RSZ;
    for (int i = idx; i < BN; i += nth) {
        r0_m1[i]  = 0.0f;
        r0_pmd[i] = 0.0f;
        r0_s1[i]  = 0.0f;
    }
}

// ---------------------------------------------------------------------------
// One RNN timestep. 128 blocks x 256 threads, perfectly balanced:
//   blocks [0,64)   : pmd cols 8*bid,  3 sources -> 24 K-panels of 64
//   blocks [64,128) : m1 cols (2 src, 16 panels) + s1 cols (1 src, 8 panels)
// Thread tile: 4 rows x 8 cols, K split 16 ways (kh = tid>>4, rg = tid&15).
// Inner loop per k: 1 LDS.128 (a) + 2 LDS.128 (w) + 4 packs + 16 fma.f32x2.
// A staged k-major (from g_rA) -> conflict-free float4 STS, double-buffered.
// K-reduction: shfl.xor(16) pair-reduce, then padded smem (Red[8][64][9]).
// ---------------------------------------------------------------------------
__global__ void __launch_bounds__(256,1) step_kernel(
    int t,
    const float* __restrict__ W_rec_m1,
    const float* __restrict__ W_rec_pmd,
    const float* __restrict__ W_rec_s1,
    const float* __restrict__ W_pmd_m1,
    const float* __restrict__ b_pmd_m1,
    const float* __restrict__ W_s1_pmd,
    const float* __restrict__ W_in_s1,
    const float* __restrict__ b_in_s1,
    const float* __restrict__ stim,
    float* __restrict__ d_out)
{
    __shared__ float As[2][64][64];   // [buf][kk][batch] k-major
    __shared__ float Ws[2][64][8];    // [buf][kk][col]
    __shared__ float stim_s[BATCH][D_IN];

    const int tid = threadIdx.x;
    const int bid = blockIdx.x;
    const int pr  = (t-1)&1, pw = t&1;
    const int kh  = tid >> 4;         // 16 k-slices
    const int rg  = tid & 15;         // 16 row-groups (4 rows each)

    const float* Aseg[3];
    const float* Wseg[3];
    int jb;

    // combined blocks need the stimulus for the s1 epilogue
    if (bid >= 64) {
        for (int i = tid; i < BATCH*D_IN; i += 256)
            (&stim_s[0][0])[i] = stim[t*BATCH*D_IN + i];
    }

    auto run_group = [&](int nseg, int reg, const float* bias, bool add_stim) {
        u64 acc[4][4];
        #pragma unroll
        for (int r = 0; r < 4; r++)
            #pragma unroll
            for (int c = 0; c < 4; c++) acc[r][c] = 0ull;

        const int np = nseg*8;
        float4 Ar[4]; float4 Wr;

        auto ldg = [&](int p) {
            const float* A = Aseg[p>>3];
            int k0 = (p&7) << 6;
            #pragma unroll
            for (int i = 0; i < 4; i++) {
                int idx = tid + (i<<8);
                Ar[i] = *(const float4*)&A[((k0 + (idx>>4))<<6) + ((idx&15)<<2)];
            }
            if (tid < 128) {
                const float* W = Wseg[p>>3];
                Wr = *(const float4*)&W[(k0 + (tid>>1))*NH + jb + ((tid&1)<<2)];
            }
        };
        auto sts = [&](int p) {
            int buf = p & 1;
            #pragma unroll
            for (int i = 0; i < 4; i++) {
                int idx = tid + (i<<8);
                *(float4*)&As[buf][idx>>4][(idx&15)<<2] = Ar[i];
            }
            if (tid < 128)
                *(float4*)&Ws[buf][tid>>1][(tid&1)<<2] = Wr;
        };

        ldg(0); sts(0); __syncthreads();

        for (int p = 0; p < np; p++) {
            int buf = p & 1;
            if (p + 1 < np) ldg(p + 1);
            #pragma unroll
            for (int i = 0; i < 4; i++) {
                int kk = (kh<<2) + i;
                float4 av = *(const float4*)&As[buf][kk][rg<<2];
                ulonglong2 wA = *(const ulonglong2*)&Ws[buf][kk][0];
                ulonglong2 wB = *(const ulonglong2*)&Ws[buf][kk][4];
                u64 a0 = pk2(av.x, av.x);
                u64 a1 = pk2(av.y, av.y);
                u64 a2 = pk2(av.z, av.z);
                u64 a3 = pk2(av.w, av.w);
                fma2(acc[0][0],a0,wA.x); fma2(acc[0][1],a0,wA.y);
                fma2(acc[0][2],a0,wB.x); fma2(acc[0][3],a0,wB.y);
                fma2(acc[1][0],a1,wA.x); fma2(acc[1][1],a1,wA.y);
                fma2(acc[1][2],a1,wB.x); fma2(acc[1][3],a1,wB.y);
                fma2(acc[2][0],a2,wA.x); fma2(acc[2][1],a2,wA.y);
                fma2(acc[2][2],a2,wB.x); fma2(acc[2][3],a2,wB.y);
                fma2(acc[3][0],a3,wA.x); fma2(acc[3][1],a3,wA.y);
                fma2(acc[3][2],a3,wB.x); fma2(acc[3][3],a3,wB.y);
            }
            if (p + 1 < np) sts(p + 1);
            __syncthreads();
        }

        // ---- reduce 16 k-slices -> output ----
        // pair-reduce kh (2w, 2w+1) within each warp
        #pragma unroll
        for (int r = 0; r < 4; r++)
            #pragma unroll
            for (int c = 0; c < 4; c++)
                acc[r][c] = add2(acc[r][c],
                                 __shfl_xor_sync(0xffffffffu, acc[r][c], 16));

        float (*Red)[64][9] = reinterpret_cast<float (*)[64][9]>(&As[0][0][0]);
        const int w = tid >> 5;
        if ((tid & 16) == 0) {
            #pragma unroll
            for (int r = 0; r < 4; r++)
                #pragma unroll
                for (int c = 0; c < 4; c++) {
                    float2 v = upk2(acc[r][c]);
                    Red[w][(rg<<2)+r][2*c]   = v.x;
                    Red[w][(rg<<2)+r][2*c+1] = v.y;
                }
        }
        __syncthreads();

        float* rates = d_out + OUTS_SZ + (size_t)reg*RSZ + (size_t)t*BN;
        #pragma unroll
        for (int o = tid; o < 512; o += 256) {
            int b = o >> 3, j = o & 7, jj = jb + j;
            float s = 0.f;
            #pragma unroll
            for (int q = 0; q < 8; q++) s += Red[q][b][j];
            float v = s + bias[jj];
            if (add_stim) {
                #pragma unroll
                for (int k = 0; k < D_IN; k++)
                    v = fmaf(stim_s[b][k], W_in_s1[k*NH + jj], v);
            }
            float x = g_X[reg][b][jj];
            x = 0.8f*x + 0.2f*v;
            g_X[reg][b][jj] = x;
            float rr = tanhf(x);
            rates[b*NH + jj]     = rr;   // [T,B,N] output layout
            g_rA[pw][reg][jj][b] = rr;   // k-major for next step
        }
        __syncthreads();
    };

    if (bid < 64) {                        // pmd (reg=1): 3 sources
        jb = bid << 3;
        Aseg[0] = &g_rA[pr][1][0][0]; Wseg[0] = W_rec_pmd;
        Aseg[1] = &g_rA[pr][0][0][0]; Wseg[1] = g_Wm1pmd_c;   // fb folded
        Aseg[2] = &g_rA[pr][2][0][0]; Wseg[2] = W_s1_pmd;
        run_group(3, 1, (t==1) ? g_bias_pmd_t1 : g_bias_pmd, false);
    } else {                               // m1 (2 src) then s1 (1 src)
        jb = (bid - 64) << 3;
        Aseg[0] = &g_rA[pr][0][0][0]; Wseg[0] = W_rec_m1;
        Aseg[1] = &g_rA[pr][1][0][0]; Wseg[1] = W_pmd_m1;
        run_group(2, 0, b_pmd_m1, false);
        Aseg[0] = &g_rA[pr][2][0][0]; Wseg[0] = W_rec_s1;
        run_group(1, 2, b_in_s1, true);
    }
}

// ---------------------------------------------------------------------------
// Readout: outs[t] = r_m1[t] @ W_out + b_out (t>=1); zeros at t=0.
// ---------------------------------------------------------------------------
__global__ void finale_kernel(const float* __restrict__ W_out,
                              const float* __restrict__ b_out,
                              float* __restrict__ d_out)
{
    const int t = blockIdx.x;
    const int u = threadIdx.x;       // 0..127
    const int b = u >> 1, d = u & 1;

    if (t == 0) { d_out[u] = 0.0f; return; }

    const float* rm = d_out + OUTS_SZ + (size_t)t*BN + b*NH;
    float a0=0.f, a1=0.f, a2=0.f, a3=0.f;
    for (int k = 0; k < NH; k += 4) {
        float4 r4 = *reinterpret_cast<const float4*>(&rm[k]);
        a0 = fmaf(r4.x, W_out[(k+0)*2 + d], a0);
        a1 = fmaf(r4.y, W_out[(k+1)*2 + d], a1);
        a2 = fmaf(r4.z, W_out[(k+2)*2 + d], a2);
        a3 = fmaf(r4.w, W_out[(k+3)*2 + d], a3);
    }
    d_out[t*BATCH*D_OUT + b*D_OUT + d] = b_out[d] + (a0 + a1) + (a2 + a3);
}

// ---------------------------------------------------------------------------
extern "C" void kernel_launch(void* const* d_in, const int* in_sizes, int n_in,
                              void* d_out, int out_size)
{
    const float* stim      = (const float*)d_in[0];
    const float* W_rec_m1  = (const float*)d_in[1];
    const float* W_rec_pmd = (const float*)d_in[2];
    const float* W_rec_s1  = (const float*)d_in[3];
    const float* W_pmd_m1  = (const float*)d_in[4];
    const float* b_pmd_m1  = (const float*)d_in[5];
    const float* W_m1_pmd  = (const float*)d_in[6];
    const float* b_m1_pmd  = (const float*)d_in[7];
    const float* W_s1_pmd  = (const float*)d_in[8];
    const float* b_s1_pmd  = (const float*)d_in[9];
    const float* W_in_s1   = (const float*)d_in[10];
    const float* b_in_s1   = (const float*)d_in[11];
    const float* W_out_m1  = (const float*)d_in[12];
    const float* b_out_m1  = (const float*)d_in[13];
    const float* W_fb_pmd  = (const float*)d_in[14];
    const float* b_fb_pmd  = (const float*)d_in[15];
    float* out = (float*)d_out;

    prep_kernel<<<256, 256>>>(W_m1_pmd, W_out_m1, W_fb_pmd,
                              b_m1_pmd, b_s1_pmd, b_fb_pmd, b_out_m1, out);

    for (int t = 1; t < T_STEPS; t++) {
        step_kernel<<<128, 256>>>(t,
            W_rec_m1, W_rec_pmd, W_rec_s1,
            W_pmd_m1, b_pmd_m1, W_s1_pmd,
            W_in_s1, b_in_s1, stim, out);
    }

    finale_kernel<<<T_STEPS, 128>>>(W_out_m1, b_out_m1, out);
}

// round 5
// speedup vs baseline: 3.2297x; 2.2149x over previous
#include <cuda_runtime.h>
#include <math.h>

// Problem constants
#define T_STEPS 300
#define BATCH   64
#define NH      512
#define D_IN    10
#define D_OUT   2

#define OUTS_SZ (T_STEPS*BATCH*D_OUT)
#define RSZ     (T_STEPS*BATCH*NH)
#define BN      (BATCH*NH)
#define NBLK    128

typedef unsigned long long u64;

// Persistent device scratch (no allocation — __device__ globals)
__device__ float g_rA[2][3][NH][BATCH];     // rates, k-major, double-buffered
__device__ unsigned g_cnt = 0;              // barrier arrival counter
__device__ volatile unsigned g_gen = 0;     // barrier generation

// ---- f32x2 packed math (sm_103a) -----------------------------------------
__device__ __forceinline__ u64 pk2(float x, float y) {
    u64 r; asm("mov.b64 %0,{%1,%2};" : "=l"(r) : "f"(x), "f"(y)); return r;
}
__device__ __forceinline__ float2 upk2(u64 v) {
    float2 r; asm("mov.b64 {%0,%1},%2;" : "=f"(r.x), "=f"(r.y) : "l"(v)); return r;
}
__device__ __forceinline__ void fma2(u64 &d, u64 a, u64 b) {
    asm("fma.rn.f32x2 %0,%1,%2,%0;" : "+l"(d) : "l"(a), "l"(b));
}
__device__ __forceinline__ u64 add2(u64 a, u64 b) {
    u64 d; asm("add.rn.f32x2 %0,%1,%2;" : "=l"(d) : "l"(a), "l"(b)); return d;
}

// ---- dynamic shared memory layout -----------------------------------------
struct Smem {
    float Ws[3*NH][8];          // resident weights: 48 KB
    float Red[8][64][9];        // K-reduction scratch: 18 KB (scalar access only)
    float stim_s[BATCH][D_IN];  // current stimulus: 2.5 KB
    float Win[D_IN][8];         // W_in_s1 columns: 320 B
};

// ---- grid barrier (all 128 blocks resident; 1 block/SM) -------------------
__device__ __forceinline__ void grid_bar(unsigned* mygen) {
    __threadfence();                       // publish this thread's .cg stores
    __syncthreads();
    if (threadIdx.x == 0) {
        unsigned g = *mygen;
        unsigned old = atomicAdd(&g_cnt, 1);
        if (old == NBLK-1) { g_cnt = 0; __threadfence(); g_gen = g + 1; }
        else { while (g_gen == g) __nanosleep(32); }
    }
    __syncthreads();
    (*mygen)++;
}

// ---- GEMM accumulate: NSEG sources of 8 panels (64 k each) ----------------
// Thread (kh=tid>>4, rg=tid&15): 4 k-values x 4 batch x 8 cols per panel.
// A read straight from L2 (__ldcg, coalesced); W from smem broadcast.
// Inner: per k = 2 LDS.128 + 4 packs + 16 fma.f32x2.
template<int NSEG>
__device__ __forceinline__ void compute_accum(
    const float* __restrict__ A0, const float* __restrict__ A1,
    const float* __restrict__ A2, int wbase,
    const float (* __restrict__ Ws)[8], int kh, int rg, u64 acc[4][4])
{
    #pragma unroll
    for (int r = 0; r < 4; r++)
        #pragma unroll
        for (int c = 0; c < 4; c++) acc[r][c] = 0ull;

    const int np = NSEG*8;
    float4 cur[4], nxt[4];

    #pragma unroll
    for (int i = 0; i < 4; i++)
        cur[i] = __ldcg((const float4*)&A0[(kh*4 + i)*BATCH + rg*4]);

    for (int p = 0; p < np; p++) {
        if (p + 1 < np) {
            int s = (p+1) >> 3;
            const float* Ap = (s == 0) ? A0 : (s == 1) ? A1 : A2;
            int k0 = ((p+1) & 7) << 6;
            #pragma unroll
            for (int i = 0; i < 4; i++)
                nxt[i] = __ldcg((const float4*)&Ap[(k0 + kh*4 + i)*BATCH + rg*4]);
        }
        #pragma unroll
        for (int i = 0; i < 4; i++) {
            int wr = wbase + p*64 + kh*4 + i;
            ulonglong2 wA = *(const ulonglong2*)&Ws[wr][0];
            ulonglong2 wB = *(const ulonglong2*)&Ws[wr][4];
            float4 av = cur[i];
            u64 a0 = pk2(av.x, av.x);
            u64 a1 = pk2(av.y, av.y);
            u64 a2 = pk2(av.z, av.z);
            u64 a3 = pk2(av.w, av.w);
            fma2(acc[0][0],a0,wA.x); fma2(acc[0][1],a0,wA.y);
            fma2(acc[0][2],a0,wB.x); fma2(acc[0][3],a0,wB.y);
            fma2(acc[1][0],a1,wA.x); fma2(acc[1][1],a1,wA.y);
            fma2(acc[1][2],a1,wB.x); fma2(acc[1][3],a1,wB.y);
            fma2(acc[2][0],a2,wA.x); fma2(acc[2][1],a2,wA.y);
            fma2(acc[2][2],a2,wB.x); fma2(acc[2][3],a2,wB.y);
            fma2(acc[3][0],a3,wA.x); fma2(acc[3][1],a3,wA.y);
            fma2(acc[3][2],a3,wB.x); fma2(acc[3][3],a3,wB.y);
        }
        #pragma unroll
        for (int i = 0; i < 4; i++) cur[i] = nxt[i];
    }
}

// ---- epilogue: reduce 16 k-slices, leaky update, tanh, write rates --------
__device__ __forceinline__ void epilogue(
    int reg, u64 acc[4][4], float biasv, bool add_stim,
    Smem& sm, int t, int pw, int jj, float& x0, float& x1,
    float* __restrict__ d_out)
{
    const int tid = threadIdx.x;
    const int w = tid >> 5, rg = tid & 15;

    // pair-reduce kh (2w, 2w+1) within the warp
    #pragma unroll
    for (int r = 0; r < 4; r++)
        #pragma unroll
        for (int c = 0; c < 4; c++)
            acc[r][c] = add2(acc[r][c], __shfl_xor_sync(0xffffffffu, acc[r][c], 16));

    if ((tid & 16) == 0) {
        #pragma unroll
        for (int r = 0; r < 4; r++)
            #pragma unroll
            for (int c = 0; c < 4; c++) {
                float2 v = upk2(acc[r][c]);
                // scalar stores: Red rows are 9 floats (36 B) -> float2 would
                // be 8B-misaligned on odd rows (R3 failure). Keep scalars.
                sm.Red[w][rg*4 + r][2*c]   = v.x;
                sm.Red[w][rg*4 + r][2*c+1] = v.y;
            }
    }
    __syncthreads();

    const int j = tid & 7;
    float* rates = d_out + OUTS_SZ + (size_t)reg*RSZ + (size_t)t*BN;
    float* gw = &g_rA[pw][reg][jj][0];

    #pragma unroll
    for (int h = 0; h < 2; h++) {
        int b = (tid >> 3) + h*32;
        float s = 0.f;
        #pragma unroll
        for (int q = 0; q < 8; q++) s += sm.Red[q][b][j];
        float v = s + biasv;
        if (add_stim) {
            #pragma unroll
            for (int k = 0; k < D_IN; k++)
                v = fmaf(sm.stim_s[b][k], sm.Win[k][j], v);
        }
        float& x = h ? x1 : x0;
        x = 0.8f*x + 0.2f*v;
        float rr = tanhf(x);
        rates[b*NH + jj] = rr;        // [T,B,N] output layout
        __stcg(&gw[b], rr);           // k-major for next step (L2 coherent)
    }
    __syncthreads();
}

// ---------------------------------------------------------------------------
// Persistent RNN kernel: weights resident in smem, X state in registers,
// 299 steps separated by one grid barrier each.
//   blocks [0,64)   : pmd cols 8*bid   (3 sources, 24 panels)
//   blocks [64,128) : m1 cols (2 src, 16 panels) + s1 cols (1 src, 8 panels)
// ---------------------------------------------------------------------------
__global__ void __launch_bounds__(256,1) rnn_persistent(
    const float* __restrict__ W_rec_m1, const float* __restrict__ W_rec_pmd,
    const float* __restrict__ W_rec_s1, const float* __restrict__ W_pmd_m1,
    const float* __restrict__ b_pmd_m1, const float* __restrict__ W_m1_pmd,
    const float* __restrict__ b_m1_pmd, const float* __restrict__ W_s1_pmd,
    const float* __restrict__ b_s1_pmd, const float* __restrict__ W_in_s1,
    const float* __restrict__ b_in_s1, const float* __restrict__ W_out,
    const float* __restrict__ b_out,   const float* __restrict__ W_fb,
    const float* __restrict__ b_fb,    const float* __restrict__ stim,
    float* __restrict__ d_out)
{
    extern __shared__ char sraw[];
    Smem& sm = *reinterpret_cast<Smem*>(sraw);

    const int tid = threadIdx.x, bid = blockIdx.x;
    const bool pmdB = bid < 64;
    const int jb = (pmdB ? bid : bid - 64) << 3;
    const int jj = jb + (tid & 7);

    // ---- load weights into smem (once) ----
    if (pmdB) {
        for (int r = tid; r < NH; r += 256) {
            float wo0 = W_out[r*2], wo1 = W_out[r*2+1];
            #pragma unroll
            for (int q = 0; q < 8; q++) {
                int col = jb + q;
                sm.Ws[r][q]        = W_rec_pmd[r*NH + col];
                sm.Ws[NH + r][q]   = W_m1_pmd[r*NH + col]
                                   + wo0*W_fb[col] + wo1*W_fb[NH + col];
                sm.Ws[2*NH + r][q] = W_s1_pmd[r*NH + col];
            }
        }
    } else {
        for (int r = tid; r < NH; r += 256) {
            #pragma unroll
            for (int q = 0; q < 8; q++) {
                int col = jb + q;
                sm.Ws[r][q]        = W_rec_m1[r*NH + col];
                sm.Ws[NH + r][q]   = W_pmd_m1[r*NH + col];
                sm.Ws[2*NH + r][q] = W_rec_s1[r*NH + col];
            }
        }
        for (int i = tid; i < D_IN*8; i += 256)
            sm.Win[i>>3][i&7] = W_in_s1[(i>>3)*NH + jb + (i&7)];
    }

    // ---- fold biases into registers ----
    float bias0, bias_ex = 0.f, bias_s1 = 0.f;
    if (pmdB) {
        bias0   = b_m1_pmd[jj] + b_s1_pmd[jj] + b_fb[jj];
        bias_ex = b_out[0]*W_fb[jj] + b_out[1]*W_fb[NH + jj];
    } else {
        bias0   = b_pmd_m1[jj];
        bias_s1 = b_in_s1[jj];
    }

    // ---- zero parity-0 rates and t=0 output slices ----
    {
        float* rA0 = &g_rA[0][0][0][0];
        for (int i = bid*256 + tid; i < 3*NH*BATCH; i += NBLK*256)
            __stcg(&rA0[i], 0.f);
        float* r0 = d_out + OUTS_SZ;
        for (int i = bid*256 + tid; i < BN; i += NBLK*256) {
            r0[i] = 0.f; r0[RSZ + i] = 0.f; r0[2*RSZ + i] = 0.f;
        }
        if (bid == 0 && tid < BATCH*D_OUT) d_out[tid] = 0.f;
    }

    float x_a0 = 0.f, x_a1 = 0.f;   // pmd (pmd-block) / m1 (m1s1-block)
    float x_b0 = 0.f, x_b1 = 0.f;   // s1 (m1s1-block)

    unsigned mygen = g_gen;
    grid_bar(&mygen);

    const int kh = tid >> 4, rg = tid & 15;
    u64 acc[4][4];

    for (int t = 1; t < T_STEPS; t++) {
        const int pr = (t-1) & 1, pw = t & 1;
        const float* Am1  = &g_rA[pr][0][0][0];
        const float* Apmd = &g_rA[pr][1][0][0];
        const float* As1  = &g_rA[pr][2][0][0];

        if (pmdB) {
            // pmd: r_pmd@W_rec_pmd + r_m1@(W_m1_pmd+fb) + r_s1@W_s1_pmd
            compute_accum<3>(Apmd, Am1, As1, 0, sm.Ws, kh, rg, acc);
            float bv = (t == 1) ? bias0 : (bias0 + bias_ex);
            epilogue(1, acc, bv, false, sm, t, pw, jj, x_a0, x_a1, d_out);
        } else {
            // stage current stimulus (640 floats) for the s1 epilogue
            if (tid < 160)
                ((float4*)&sm.stim_s[0][0])[tid] =
                    __ldg((const float4*)(stim + (size_t)t*BATCH*D_IN) + tid);
            // m1: r_m1@W_rec_m1 + r_pmd@W_pmd_m1
            compute_accum<2>(Am1, Apmd, Apmd, 0, sm.Ws, kh, rg, acc);
            epilogue(0, acc, bias0, false, sm, t, pw, jj, x_a0, x_a1, d_out);
            // s1: r_s1@W_rec_s1 + stim@W_in_s1
            compute_accum<1>(As1, As1, As1, 2*NH, sm.Ws, kh, rg, acc);
            epilogue(2, acc, bias_s1, true, sm, t, pw, jj, x_b0, x_b1, d_out);
        }
        grid_bar(&mygen);
    }
}

// ---------------------------------------------------------------------------
// Readout: outs[t] = r_m1[t] @ W_out + b_out (t>=1); zeros at t=0.
// ---------------------------------------------------------------------------
__global__ void finale_kernel(const float* __restrict__ W_out,
                              const float* __restrict__ b_out,
                              float* __restrict__ d_out)
{
    const int t = blockIdx.x;
    const int u = threadIdx.x;       // 0..127
    const int b = u >> 1, d = u & 1;

    if (t == 0) { d_out[u] = 0.0f; return; }

    const float* rm = d_out + OUTS_SZ + (size_t)t*BN + b*NH;
    float a0=0.f, a1=0.f, a2=0.f, a3=0.f;
    for (int k = 0; k < NH; k += 4) {
        float4 r4 = *reinterpret_cast<const float4*>(&rm[k]);
        a0 = fmaf(r4.x, W_out[(k+0)*2 + d], a0);
        a1 = fmaf(r4.y, W_out[(k+1)*2 + d], a1);
        a2 = fmaf(r4.z, W_out[(k+2)*2 + d], a2);
        a3 = fmaf(r4.w, W_out[(k+3)*2 + d], a3);
    }
    d_out[t*BATCH*D_OUT + b*D_OUT + d] = b_out[d] + (a0 + a1) + (a2 + a3);
}

// ---------------------------------------------------------------------------
extern "C" void kernel_launch(void* const* d_in, const int* in_sizes, int n_in,
                              void* d_out, int out_size)
{
    const float* stim      = (const float*)d_in[0];
    const float* W_rec_m1  = (const float*)d_in[1];
    const float* W_rec_pmd = (const float*)d_in[2];
    const float* W_rec_s1  = (const float*)d_in[3];
    const float* W_pmd_m1  = (const float*)d_in[4];
    const float* b_pmd_m1  = (const float*)d_in[5];
    const float* W_m1_pmd  = (const float*)d_in[6];
    const float* b_m1_pmd  = (const float*)d_in[7];
    const float* W_s1_pmd  = (const float*)d_in[8];
    const float* b_s1_pmd  = (const float*)d_in[9];
    const float* W_in_s1   = (const float*)d_in[10];
    const float* b_in_s1   = (const float*)d_in[11];
    const float* W_out_m1  = (const float*)d_in[12];
    const float* b_out_m1  = (const float*)d_in[13];
    const float* W_fb_pmd  = (const float*)d_in[14];
    const float* b_fb_pmd  = (const float*)d_in[15];
    float* out = (float*)d_out;

    // Idempotent, capture-safe; no static guard (determinism rule).
    cudaFuncSetAttribute(rnn_persistent,
                         cudaFuncAttributeMaxDynamicSharedMemorySize,
                         (int)sizeof(Smem));

    rnn_persistent<<<NBLK, 256, sizeof(Smem)>>>(
        W_rec_m1, W_rec_pmd, W_rec_s1, W_pmd_m1, b_pmd_m1, W_m1_pmd,
        b_m1_pmd, W_s1_pmd, b_s1_pmd, W_in_s1, b_in_s1,
        W_out_m1, b_out_m1, W_fb_pmd, b_fb_pmd, stim, out);

    finale_kernel<<<T_STEPS, 128>>>(W_out_m1, b_out_m1, out);
}